// round 3
// baseline (speedup 1.0000x reference)
#include <cuda_runtime.h>
#include <cuda_bf16.h>
#include <cstdint>

#define N_NODES 100000
#define N_EDGES 1600000
#define H 128

// Scratch: device globals (no allocation allowed). 16B-aligned for v4 RED / float4.
__device__ __align__(16) float g_agg[(size_t)N_NODES * H];
__device__ __align__(16) float g_h1[(size_t)N_NODES * H];

// ---------------------------------------------------------------------------
// Kernel 1: agg = x   (EPS=0 -> (1+EPS)*x = x), vectorized copy
// ---------------------------------------------------------------------------
__global__ void init_agg_kernel(const float* __restrict__ x) {
    size_t i = (size_t)blockIdx.x * blockDim.x + threadIdx.x;
    size_t n4 = (size_t)N_NODES * H / 4;
    const float4* x4 = (const float4*)x;
    float4* a4 = (float4*)g_agg;
    for (; i < n4; i += (size_t)gridDim.x * blockDim.x) {
        a4[i] = x4[i];
    }
}

// ---------------------------------------------------------------------------
// Kernel 2: edge scatter. One warp per edge; lane l handles floats [4l,4l+4).
//   agg[dst] += x[src] + ew * w_edge + b_edge   (vector RED.128 atomics)
// edge_index is INT32 (JAX x64 disabled -> int64 request silently int32).
// ---------------------------------------------------------------------------
__global__ void edge_scatter_kernel(const float* __restrict__ x,
                                    const int* __restrict__ edge_index,
                                    const float* __restrict__ ew,
                                    const float* __restrict__ w_edge,
                                    const float* __restrict__ b_edge) {
    int warp_in_block = threadIdx.x >> 5;
    int lane = threadIdx.x & 31;
    long long e = (long long)blockIdx.x * (blockDim.x >> 5) + warp_in_block;
    if (e >= N_EDGES) return;

    int src = edge_index[e];
    int dst = edge_index[(long long)N_EDGES + e];
    float w = ew[e];

    const float4* xr = (const float4*)(x + (size_t)src * H);
    const float4* we4 = (const float4*)w_edge;
    const float4* be4 = (const float4*)b_edge;

    float4 xv = xr[lane];
    float4 wv = we4[lane];
    float4 bv = be4[lane];

    float4 v;
    v.x = xv.x + w * wv.x + bv.x;
    v.y = xv.y + w * wv.y + bv.y;
    v.z = xv.z + w * wv.z + bv.z;
    v.w = xv.w + w * wv.w + bv.w;

    float* dstp = g_agg + (size_t)dst * H + lane * 4;
    asm volatile("red.global.add.v4.f32 [%0], {%1,%2,%3,%4};"
                 :: "l"(dstp), "f"(v.x), "f"(v.y), "f"(v.z), "f"(v.w)
                 : "memory");
}

// ---------------------------------------------------------------------------
// Kernel 3: C = act(A @ W^T + bias), A:[nrows,128], W:[128,128] (torch layout
// [out,in]), per-block tile 64 rows x 128 cols. 256 threads, each computes
// an 8x4 register tile. W transposed into smem (Ws[k][n]); A tile in smem.
// Dynamic smem: 128*128*4 + 64*128*4 = 96 KB.
// ---------------------------------------------------------------------------
template <bool RELU>
__global__ void gemm_bias_kernel(const float* __restrict__ A,
                                 const float* __restrict__ W,
                                 const float* __restrict__ bias,
                                 float* __restrict__ C,
                                 int nrows) {
    extern __shared__ float sm[];
    float* Ws = sm;                 // [128][128] : Ws[k*128+n] = W[n*128+k]
    float* As = sm + 128 * 128;     // [64][128]  : As[r*128+k]

    int tid = threadIdx.x;
    int row0 = blockIdx.x * 64;

    // Load W transposed
    #pragma unroll 4
    for (int i = tid; i < 128 * 128; i += 256) {
        int n = i >> 7;
        int k = i & 127;
        Ws[k * 128 + n] = W[n * 128 + k];
    }
    // Load A tile
    #pragma unroll 4
    for (int i = tid; i < 64 * 128; i += 256) {
        int r = i >> 7;
        int gr = row0 + r;
        As[i] = (gr < nrows) ? A[(size_t)gr * 128 + (i & 127)] : 0.0f;
    }
    __syncthreads();

    int tx = tid & 31;   // column group: cols [4*tx, 4*tx+4)
    int ty = tid >> 5;   // row group: rows [8*ty, 8*ty+8)

    float acc[8][4];
    #pragma unroll
    for (int r = 0; r < 8; r++)
        #pragma unroll
        for (int c = 0; c < 4; c++) acc[r][c] = 0.0f;

    #pragma unroll 4
    for (int k = 0; k < 128; k++) {
        float4 wv = *(const float4*)&Ws[k * 128 + tx * 4];
        #pragma unroll
        for (int r = 0; r < 8; r++) {
            float av = As[(ty * 8 + r) * 128 + k];
            acc[r][0] += av * wv.x;
            acc[r][1] += av * wv.y;
            acc[r][2] += av * wv.z;
            acc[r][3] += av * wv.w;
        }
    }

    float4 bv = *(const float4*)&bias[tx * 4];
    #pragma unroll
    for (int r = 0; r < 8; r++) {
        int gr = row0 + ty * 8 + r;
        if (gr < nrows) {
            float4 o;
            o.x = acc[r][0] + bv.x;
            o.y = acc[r][1] + bv.y;
            o.z = acc[r][2] + bv.z;
            o.w = acc[r][3] + bv.w;
            if (RELU) {
                o.x = fmaxf(o.x, 0.0f);
                o.y = fmaxf(o.y, 0.0f);
                o.z = fmaxf(o.z, 0.0f);
                o.w = fmaxf(o.w, 0.0f);
            }
            *(float4*)&C[(size_t)gr * 128 + tx * 4] = o;
        }
    }
}

// ---------------------------------------------------------------------------
extern "C" void kernel_launch(void* const* d_in, const int* in_sizes, int n_in,
                              void* d_out, int out_size) {
    const float* x      = (const float*)d_in[0];
    const int*   ei     = (const int*)d_in[1];
    const float* ew     = (const float*)d_in[2];
    const float* w_edge = (const float*)d_in[3];
    const float* b_edge = (const float*)d_in[4];
    const float* w1     = (const float*)d_in[5];
    const float* b1     = (const float*)d_in[6];
    const float* w2     = (const float*)d_in[7];
    const float* b2     = (const float*)d_in[8];
    float*       out    = (float*)d_out;

    const int smem_bytes = (128 * 128 + 64 * 128) * sizeof(float);  // 96 KB
    cudaFuncSetAttribute(gemm_bias_kernel<true>,
                         cudaFuncAttributeMaxDynamicSharedMemorySize, smem_bytes);
    cudaFuncSetAttribute(gemm_bias_kernel<false>,
                         cudaFuncAttributeMaxDynamicSharedMemorySize, smem_bytes);

    float* agg;
    float* h1;
    cudaGetSymbolAddress((void**)&agg, g_agg);
    cudaGetSymbolAddress((void**)&h1, g_h1);

    // 1) agg = x
    init_agg_kernel<<<2048, 256>>>(x);

    // 2) scatter edges: 8 edges/block (8 warps)
    edge_scatter_kernel<<<N_EDGES / 8, 256>>>(x, ei, ew, w_edge, b_edge);

    // 3) h1 = relu(agg @ w1^T + b1)
    int gblocks = (N_NODES + 63) / 64;
    gemm_bias_kernel<true><<<gblocks, 256, smem_bytes>>>(agg, w1, b1, h1, N_NODES);

    // 4) out = h1 @ w2^T + b2
    gemm_bias_kernel<false><<<gblocks, 256, smem_bytes>>>(h1, w2, b2, out, N_NODES);
}

// round 5
// speedup vs baseline: 1.4907x; 1.4907x over previous
#include <cuda_runtime.h>
#include <cuda_bf16.h>
#include <cstdint>

#define N_NODES 100000
#define N_EDGES 1600000
#define H 128
#define NTILES ((N_NODES + 127) / 128)

// Scratch: device globals (no allocation allowed). 16B-aligned.
__device__ __align__(16) float g_agg[(size_t)N_NODES * H];
__device__ __align__(16) float g_h1[(size_t)N_NODES * H];
__device__ unsigned g_ctr1;
__device__ unsigned g_ctr2;

// ---------------------------------------------------------------------------
// Kernel 1: agg = x (EPS=0), plus reset tile counters for the GEMMs.
// ---------------------------------------------------------------------------
__global__ void init_agg_kernel(const float* __restrict__ x) {
    if (blockIdx.x == 0 && threadIdx.x == 0) { g_ctr1 = 0; g_ctr2 = 0; }
    size_t i = (size_t)blockIdx.x * blockDim.x + threadIdx.x;
    size_t n4 = (size_t)N_NODES * H / 4;
    const float4* x4 = (const float4*)x;
    float4* a4 = (float4*)g_agg;
    for (; i < n4; i += (size_t)gridDim.x * blockDim.x) {
        a4[i] = x4[i];
    }
}

// ---------------------------------------------------------------------------
// Kernel 2: edge scatter. One warp per edge; lane l handles floats [4l,4l+4).
//   agg[dst] += x[src] + ew * w_edge + b_edge   (RED.128 vector atomics)
// edge_index is int32.
// ---------------------------------------------------------------------------
__global__ void edge_scatter_kernel(const float* __restrict__ x,
                                    const int* __restrict__ edge_index,
                                    const float* __restrict__ ew,
                                    const float* __restrict__ w_edge,
                                    const float* __restrict__ b_edge) {
    int warp_in_block = threadIdx.x >> 5;
    int lane = threadIdx.x & 31;
    long long e = (long long)blockIdx.x * (blockDim.x >> 5) + warp_in_block;
    if (e >= N_EDGES) return;

    int src = edge_index[e];
    int dst = edge_index[(long long)N_EDGES + e];
    float w = ew[e];

    float4 xv = ((const float4*)(x + (size_t)src * H))[lane];
    float4 wv = ((const float4*)w_edge)[lane];
    float4 bv = ((const float4*)b_edge)[lane];

    float4 v;
    v.x = xv.x + w * wv.x + bv.x;
    v.y = xv.y + w * wv.y + bv.y;
    v.z = xv.z + w * wv.z + bv.z;
    v.w = xv.w + w * wv.w + bv.w;

    float* dstp = g_agg + (size_t)dst * H + lane * 4;
    asm volatile("red.global.add.v4.f32 [%0], {%1,%2,%3,%4};"
                 :: "l"(dstp), "f"(v.x), "f"(v.y), "f"(v.z), "f"(v.w)
                 : "memory");
}

// ---------------------------------------------------------------------------
// GEMM: C = act(A @ W^T + bias). Persistent blocks, dynamic tile counter,
// 128x128 tile, 512 threads (8 rows x 4 cols per thread), Ws padded stride
// 132 to avoid transpose-store bank conflicts, A tiles double-buffered via
// cp.async. smem = 128*132*4 + 2*128*128*4 = 194 KB -> 1 CTA/SM.
// ---------------------------------------------------------------------------
#define WS_STRIDE 132

__device__ __forceinline__ void load_As_tile(float* Asb, const float* __restrict__ A,
                                             unsigned t, int nrows, int tid) {
    #pragma unroll
    for (int i = tid; i < 4096; i += 512) {          // 4096 float4 = 64 KB
        int r = i >> 5;
        int c = (i & 31) * 4;
        int gr = (int)t * 128 + r;
        float* dgen = Asb + r * 128 + c;
        uint32_t daddr = (uint32_t)__cvta_generic_to_shared(dgen);
        if (gr < nrows) {
            const float* src = A + (size_t)gr * 128 + c;
            asm volatile("cp.async.cg.shared.global [%0], [%1], 16;"
                         :: "r"(daddr), "l"(src));
        } else {
            float4 z = make_float4(0.f, 0.f, 0.f, 0.f);
            *(float4*)dgen = z;
        }
    }
}

template <bool RELU>
__global__ __launch_bounds__(512, 1)
void gemm_persist_kernel(const float* __restrict__ A,
                         const float* __restrict__ W,
                         const float* __restrict__ bias,
                         float* __restrict__ C,
                         int nrows, unsigned* __restrict__ ctr) {
    extern __shared__ float sm[];
    float* Ws  = sm;                          // [128][WS_STRIDE]: Ws[k][n]=W[n][k]
    float* As0 = sm + 128 * WS_STRIDE;
    float* As1 = As0 + 128 * 128;

    int tid = threadIdx.x;
    int ntiles = (nrows + 127) >> 7;

    // Transpose W into smem once per block (padded stride kills conflicts)
    #pragma unroll 4
    for (int i = tid; i < 128 * 128; i += 512) {
        int n = i >> 7;
        int k = i & 127;
        Ws[k * WS_STRIDE + n] = W[i];
    }

    __shared__ unsigned s_tile;
    if (tid == 0) s_tile = atomicAdd(ctr, 1u);
    __syncthreads();
    unsigned t = s_tile;
    if (t >= (unsigned)ntiles) return;

    load_As_tile(As0, A, t, nrows, tid);
    asm volatile("cp.async.commit_group;");
    int buf = 0;

    int tx = tid & 31;       // cols [4*tx, 4*tx+4)
    int ty = tid >> 5;       // rows [8*ty, 8*ty+8)
    float4 bv = *(const float4*)&bias[tx * 4];

    while (true) {
        if (tid == 0) s_tile = atomicAdd(ctr, 1u);
        __syncthreads();                       // publish s_tile; prev compute done
        unsigned tn = s_tile;
        if (tn < (unsigned)ntiles) {
            load_As_tile(buf ? As0 : As1, A, tn, nrows, tid);
            asm volatile("cp.async.commit_group;");
            asm volatile("cp.async.wait_group 1;");
        } else {
            asm volatile("cp.async.wait_group 0;");
        }
        __syncthreads();                       // current buffer fully resident

        const float* Asb = buf ? As1 : As0;
        float acc[8][4];
        #pragma unroll
        for (int r = 0; r < 8; r++)
            #pragma unroll
            for (int c = 0; c < 4; c++) acc[r][c] = 0.0f;

        #pragma unroll 4
        for (int k = 0; k < 128; k++) {
            float4 wv = *(const float4*)&Ws[k * WS_STRIDE + tx * 4];
            #pragma unroll
            for (int r = 0; r < 8; r++) {
                float av = Asb[(ty * 8 + r) * 128 + k];
                acc[r][0] += av * wv.x;
                acc[r][1] += av * wv.y;
                acc[r][2] += av * wv.z;
                acc[r][3] += av * wv.w;
            }
        }

        #pragma unroll
        for (int r = 0; r < 8; r++) {
            int gr = (int)t * 128 + ty * 8 + r;
            if (gr < nrows) {
                float4 o;
                o.x = acc[r][0] + bv.x;
                o.y = acc[r][1] + bv.y;
                o.z = acc[r][2] + bv.z;
                o.w = acc[r][3] + bv.w;
                if (RELU) {
                    o.x = fmaxf(o.x, 0.0f);
                    o.y = fmaxf(o.y, 0.0f);
                    o.z = fmaxf(o.z, 0.0f);
                    o.w = fmaxf(o.w, 0.0f);
                }
                *(float4*)&C[(size_t)gr * 128 + tx * 4] = o;
            }
        }

        if (tn >= (unsigned)ntiles) break;
        t = tn;
        buf ^= 1;
    }
}

// ---------------------------------------------------------------------------
extern "C" void kernel_launch(void* const* d_in, const int* in_sizes, int n_in,
                              void* d_out, int out_size) {
    const float* x      = (const float*)d_in[0];
    const int*   ei     = (const int*)d_in[1];
    const float* ew     = (const float*)d_in[2];
    const float* w_edge = (const float*)d_in[3];
    const float* b_edge = (const float*)d_in[4];
    const float* w1     = (const float*)d_in[5];
    const float* b1     = (const float*)d_in[6];
    const float* w2     = (const float*)d_in[7];
    const float* b2     = (const float*)d_in[8];
    float*       out    = (float*)d_out;

    const int smem_bytes = (128 * WS_STRIDE + 2 * 128 * 128) * sizeof(float); // ~194 KB
    cudaFuncSetAttribute(gemm_persist_kernel<true>,
                         cudaFuncAttributeMaxDynamicSharedMemorySize, smem_bytes);
    cudaFuncSetAttribute(gemm_persist_kernel<false>,
                         cudaFuncAttributeMaxDynamicSharedMemorySize, smem_bytes);

    float* agg;
    float* h1;
    unsigned* ctr1;
    unsigned* ctr2;
    cudaGetSymbolAddress((void**)&agg, g_agg);
    cudaGetSymbolAddress((void**)&h1, g_h1);
    cudaGetSymbolAddress((void**)&ctr1, g_ctr1);
    cudaGetSymbolAddress((void**)&ctr2, g_ctr2);

    // 1) agg = x ; reset tile counters
    init_agg_kernel<<<2048, 256>>>(x);

    // 2) scatter edges: 8 edges/block (8 warps)
    edge_scatter_kernel<<<N_EDGES / 8, 256>>>(x, ei, ew, w_edge, b_edge);

    // 3) h1 = relu(agg @ w1^T + b1)  — persistent, dynamic tiles
    gemm_persist_kernel<true><<<152, 512, smem_bytes>>>(agg, w1, b1, h1, N_NODES, ctr1);

    // 4) out = h1 @ w2^T + b2
    gemm_persist_kernel<false><<<152, 512, smem_bytes>>>(h1, w2, b2, out, N_NODES, ctr2);
}

// round 9
// speedup vs baseline: 1.8842x; 1.2639x over previous
#include <cuda_runtime.h>
#include <cuda_bf16.h>
#include <cstdint>

#define N_NODES 100000
#define N_EDGES 1600000
#define H 128

// Scratch: device globals (no allocation allowed). 16B-aligned.
__device__ __align__(16) float g_agg[(size_t)N_NODES * H];
__device__ __align__(16) float g_h1[(size_t)N_NODES * H];
__device__ unsigned g_ctr1;
__device__ unsigned g_ctr2;

// ---------------------------------------------------------------------------
// Kernel 1: agg = x (EPS=0), plus reset tile counters for the GEMMs.
// ---------------------------------------------------------------------------
__global__ void init_agg_kernel(const float* __restrict__ x) {
    if (blockIdx.x == 0 && threadIdx.x == 0) { g_ctr1 = 0; g_ctr2 = 0; }
    size_t i = (size_t)blockIdx.x * blockDim.x + threadIdx.x;
    size_t n4 = (size_t)N_NODES * H / 4;
    const float4* x4 = (const float4*)x;
    float4* a4 = (float4*)g_agg;
    for (; i < n4; i += (size_t)gridDim.x * blockDim.x) {
        a4[i] = x4[i];
    }
}

// ---------------------------------------------------------------------------
// Kernel 2: edge scatter, 4 edges per warp for MLP=4 on the row gathers.
// Warp-uniform int4/float4 loads of indices/weights (1 request, broadcast).
//   agg[dst] += x[src] + ew * w_edge + b_edge   (RED.128 vector atomics)
// ---------------------------------------------------------------------------
__global__ void edge_scatter_kernel(const float* __restrict__ x,
                                    const int* __restrict__ edge_index,
                                    const float* __restrict__ ew,
                                    const float* __restrict__ w_edge,
                                    const float* __restrict__ b_edge) {
    int warp = blockIdx.x * (blockDim.x >> 5) + (threadIdx.x >> 5);
    int lane = threadIdx.x & 31;
    long long e0 = (long long)warp * 4;
    if (e0 >= N_EDGES) return;

    int4   s4 = *(const int4*)&edge_index[e0];
    int4   d4 = *(const int4*)&edge_index[(long long)N_EDGES + e0];
    float4 w4 = *(const float4*)&ew[e0];

    float4 wv = ((const float4*)w_edge)[lane];
    float4 bv = ((const float4*)b_edge)[lane];

    // Issue all 4 gathers back-to-back (independent, MLP=4)
    float4 xv0 = ((const float4*)(x + (size_t)s4.x * H))[lane];
    float4 xv1 = ((const float4*)(x + (size_t)s4.y * H))[lane];
    float4 xv2 = ((const float4*)(x + (size_t)s4.z * H))[lane];
    float4 xv3 = ((const float4*)(x + (size_t)s4.w * H))[lane];

    #define DO_EDGE(XV, WSC, DST)                                              \
    {                                                                          \
        float4 v;                                                              \
        v.x = XV.x + WSC * wv.x + bv.x;                                        \
        v.y = XV.y + WSC * wv.y + bv.y;                                        \
        v.z = XV.z + WSC * wv.z + bv.z;                                        \
        v.w = XV.w + WSC * wv.w + bv.w;                                        \
        float* p = g_agg + (size_t)(DST) * H + lane * 4;                       \
        asm volatile("red.global.add.v4.f32 [%0], {%1,%2,%3,%4};"              \
                     :: "l"(p), "f"(v.x), "f"(v.y), "f"(v.z), "f"(v.w)         \
                     : "memory");                                              \
    }
    DO_EDGE(xv0, w4.x, d4.x)
    DO_EDGE(xv1, w4.y, d4.y)
    DO_EDGE(xv2, w4.z, d4.z)
    DO_EDGE(xv3, w4.w, d4.w)
    #undef DO_EDGE
}

// ---------------------------------------------------------------------------
// GEMM: C = act(A @ W^T + bias). Persistent blocks, dynamic tile counter,
// 128x128 tile, 512 threads (8 rows x 4 cols per thread), Ws padded stride
// 132, A tiles double-buffered via cp.async. Inner loop processes k in
// chunks of 4 with float4 loads of A and W (12 LDS.128 / 128 FFMA).
// smem = 128*132*4 + 2*128*128*4 = 197632 B -> 1 CTA/SM.
// ---------------------------------------------------------------------------
#define WS_STRIDE 132

__device__ __forceinline__ void load_As_tile(float* Asb, const float* __restrict__ A,
                                             unsigned t, int nrows, int tid) {
    #pragma unroll
    for (int i = tid; i < 4096; i += 512) {          // 4096 float4 = 64 KB
        int r = i >> 5;
        int c = (i & 31) * 4;
        int gr = (int)t * 128 + r;
        float* dgen = Asb + r * 128 + c;
        uint32_t daddr = (uint32_t)__cvta_generic_to_shared(dgen);
        if (gr < nrows) {
            const float* src = A + (size_t)gr * 128 + c;
            asm volatile("cp.async.cg.shared.global [%0], [%1], 16;"
                         :: "r"(daddr), "l"(src));
        } else {
            float4 z = make_float4(0.f, 0.f, 0.f, 0.f);
            *(float4*)dgen = z;
        }
    }
}

template <bool RELU>
__global__ __launch_bounds__(512, 1)
void gemm_persist_kernel(const float* __restrict__ A,
                         const float* __restrict__ W,
                         const float* __restrict__ bias,
                         float* __restrict__ C,
                         int nrows, unsigned* __restrict__ ctr) {
    extern __shared__ float sm[];
    float* Ws  = sm;                          // [128][WS_STRIDE]: Ws[k][n]=W[n][k]
    float* As0 = sm + 128 * WS_STRIDE;
    float* As1 = As0 + 128 * 128;

    int tid = threadIdx.x;
    int ntiles = (nrows + 127) >> 7;

    // Transpose W into smem once per block (padded stride kills conflicts)
    #pragma unroll 4
    for (int i = tid; i < 128 * 128; i += 512) {
        int n = i >> 7;
        int k = i & 127;
        Ws[k * WS_STRIDE + n] = W[i];
    }

    __shared__ unsigned s_tile;
    if (tid == 0) s_tile = atomicAdd(ctr, 1u);
    __syncthreads();
    unsigned t = s_tile;
    if (t >= (unsigned)ntiles) return;

    load_As_tile(As0, A, t, nrows, tid);
    asm volatile("cp.async.commit_group;");
    int buf = 0;

    int tx = tid & 31;       // cols [4*tx, 4*tx+4)
    int ty = tid >> 5;       // rows [8*ty, 8*ty+8)
    float4 bv = *(const float4*)&bias[tx * 4];

    while (true) {
        if (tid == 0) s_tile = atomicAdd(ctr, 1u);
        __syncthreads();                       // publish s_tile; prev compute done
        unsigned tn = s_tile;
        if (tn < (unsigned)ntiles) {
            load_As_tile(buf ? As0 : As1, A, tn, nrows, tid);
            asm volatile("cp.async.commit_group;");
            asm volatile("cp.async.wait_group 1;");
        } else {
            asm volatile("cp.async.wait_group 0;");
        }
        __syncthreads();                       // current buffer fully resident

        const float* Asb = buf ? As1 : As0;
        float acc[8][4];
        #pragma unroll
        for (int r = 0; r < 8; r++)
            #pragma unroll
            for (int c = 0; c < 4; c++) acc[r][c] = 0.0f;

        #pragma unroll 4
        for (int k0 = 0; k0 < 128; k0 += 4) {
            float4 wv0 = *(const float4*)&Ws[(k0 + 0) * WS_STRIDE + tx * 4];
            float4 wv1 = *(const float4*)&Ws[(k0 + 1) * WS_STRIDE + tx * 4];
            float4 wv2 = *(const float4*)&Ws[(k0 + 2) * WS_STRIDE + tx * 4];
            float4 wv3 = *(const float4*)&Ws[(k0 + 3) * WS_STRIDE + tx * 4];
            #pragma unroll
            for (int r = 0; r < 8; r++) {
                float4 a4 = *(const float4*)&Asb[(ty * 8 + r) * 128 + k0];
                acc[r][0] += a4.x * wv0.x; acc[r][1] += a4.x * wv0.y;
                acc[r][2] += a4.x * wv0.z; acc[r][3] += a4.x * wv0.w;
                acc[r][0] += a4.y * wv1.x; acc[r][1] += a4.y * wv1.y;
                acc[r][2] += a4.y * wv1.z; acc[r][3] += a4.y * wv1.w;
                acc[r][0] += a4.z * wv2.x; acc[r][1] += a4.z * wv2.y;
                acc[r][2] += a4.z * wv2.z; acc[r][3] += a4.z * wv2.w;
                acc[r][0] += a4.w * wv3.x; acc[r][1] += a4.w * wv3.y;
                acc[r][2] += a4.w * wv3.z; acc[r][3] += a4.w * wv3.w;
            }
        }

        #pragma unroll
        for (int r = 0; r < 8; r++) {
            int gr = (int)t * 128 + ty * 8 + r;
            if (gr < nrows) {
                float4 o;
                o.x = acc[r][0] + bv.x;
                o.y = acc[r][1] + bv.y;
                o.z = acc[r][2] + bv.z;
                o.w = acc[r][3] + bv.w;
                if (RELU) {
                    o.x = fmaxf(o.x, 0.0f);
                    o.y = fmaxf(o.y, 0.0f);
                    o.z = fmaxf(o.z, 0.0f);
                    o.w = fmaxf(o.w, 0.0f);
                }
                *(float4*)&C[(size_t)gr * 128 + tx * 4] = o;
            }
        }

        if (tn >= (unsigned)ntiles) break;
        t = tn;
        buf ^= 1;
    }
}

// ---------------------------------------------------------------------------
extern "C" void kernel_launch(void* const* d_in, const int* in_sizes, int n_in,
                              void* d_out, int out_size) {
    const float* x      = (const float*)d_in[0];
    const int*   ei     = (const int*)d_in[1];
    const float* ew     = (const float*)d_in[2];
    const float* w_edge = (const float*)d_in[3];
    const float* b_edge = (const float*)d_in[4];
    const float* w1     = (const float*)d_in[5];
    const float* b1     = (const float*)d_in[6];
    const float* w2     = (const float*)d_in[7];
    const float* b2     = (const float*)d_in[8];
    float*       out    = (float*)d_out;

    const int smem_bytes = (128 * WS_STRIDE + 2 * 128 * 128) * sizeof(float);
    cudaFuncSetAttribute(gemm_persist_kernel<true>,
                         cudaFuncAttributeMaxDynamicSharedMemorySize, smem_bytes);
    cudaFuncSetAttribute(gemm_persist_kernel<false>,
                         cudaFuncAttributeMaxDynamicSharedMemorySize, smem_bytes);

    float* agg;
    float* h1;
    unsigned* ctr1;
    unsigned* ctr2;
    cudaGetSymbolAddress((void**)&agg, g_agg);
    cudaGetSymbolAddress((void**)&h1, g_h1);
    cudaGetSymbolAddress((void**)&ctr1, g_ctr1);
    cudaGetSymbolAddress((void**)&ctr2, g_ctr2);

    // 1) agg = x ; reset tile counters
    init_agg_kernel<<<2048, 256>>>(x);

    // 2) scatter edges: 4 edges/warp, 8 warps/block -> 32 edges/block
    edge_scatter_kernel<<<N_EDGES / 32, 256>>>(x, ei, ew, w_edge, b_edge);

    // 3) h1 = relu(agg @ w1^T + b1)  — persistent, dynamic tiles
    gemm_persist_kernel<true><<<152, 512, smem_bytes>>>(agg, w1, b1, h1, N_NODES, ctr1);

    // 4) out = h1 @ w2^T + b2
    gemm_persist_kernel<false><<<152, 512, smem_bytes>>>(h1, w2, b2, out, N_NODES, ctr2);
}

// round 12
// speedup vs baseline: 2.6790x; 1.4218x over previous
#include <cuda_runtime.h>
#include <cstdint>

#define N_NODES 100000
#define N_EDGES 1600000
#define H 128
#define AS_STRIDE 132

// Scratch: device globals (no allocation allowed). 16B-aligned.
__device__ __align__(16) float g_agg[(size_t)N_NODES * H];
__device__ __align__(16) float g_h1[(size_t)N_NODES * H];
__device__ unsigned g_ctr1;
__device__ unsigned g_ctr2;

// ---------------------------------------------------------------------------
// Kernel 1: agg = x (EPS=0), plus reset tile counters for the GEMMs.
// ---------------------------------------------------------------------------
__global__ void init_agg_kernel(const float* __restrict__ x) {
    if (blockIdx.x == 0 && threadIdx.x == 0) { g_ctr1 = 0; g_ctr2 = 0; }
    size_t i = (size_t)blockIdx.x * blockDim.x + threadIdx.x;
    size_t n4 = (size_t)N_NODES * H / 4;
    const float4* x4 = (const float4*)x;
    float4* a4 = (float4*)g_agg;
    for (; i < n4; i += (size_t)gridDim.x * blockDim.x) {
        a4[i] = x4[i];
    }
}

// ---------------------------------------------------------------------------
// Kernel 2: edge scatter, 4 edges per warp (MLP=4), RED.128 vector atomics.
// ---------------------------------------------------------------------------
__global__ void edge_scatter_kernel(const float* __restrict__ x,
                                    const int* __restrict__ edge_index,
                                    const float* __restrict__ ew,
                                    const float* __restrict__ w_edge,
                                    const float* __restrict__ b_edge) {
    int warp = blockIdx.x * (blockDim.x >> 5) + (threadIdx.x >> 5);
    int lane = threadIdx.x & 31;
    long long e0 = (long long)warp * 4;
    if (e0 >= N_EDGES) return;

    int4   s4 = *(const int4*)&edge_index[e0];
    int4   d4 = *(const int4*)&edge_index[(long long)N_EDGES + e0];
    float4 w4 = *(const float4*)&ew[e0];

    float4 wv = ((const float4*)w_edge)[lane];
    float4 bv = ((const float4*)b_edge)[lane];

    float4 xv0 = ((const float4*)(x + (size_t)s4.x * H))[lane];
    float4 xv1 = ((const float4*)(x + (size_t)s4.y * H))[lane];
    float4 xv2 = ((const float4*)(x + (size_t)s4.z * H))[lane];
    float4 xv3 = ((const float4*)(x + (size_t)s4.w * H))[lane];

    #define DO_EDGE(XV, WSC, DST)                                              \
    {                                                                          \
        float4 v;                                                              \
        v.x = XV.x + WSC * wv.x + bv.x;                                        \
        v.y = XV.y + WSC * wv.y + bv.y;                                        \
        v.z = XV.z + WSC * wv.z + bv.z;                                        \
        v.w = XV.w + WSC * wv.w + bv.w;                                        \
        float* p = g_agg + (size_t)(DST) * H + lane * 4;                       \
        asm volatile("red.global.add.v4.f32 [%0], {%1,%2,%3,%4};"              \
                     :: "l"(p), "f"(v.x), "f"(v.y), "f"(v.z), "f"(v.w)         \
                     : "memory");                                              \
    }
    DO_EDGE(xv0, w4.x, d4.x)
    DO_EDGE(xv1, w4.y, d4.y)
    DO_EDGE(xv2, w4.z, d4.z)
    DO_EDGE(xv3, w4.w, d4.w)
    #undef DO_EDGE
}

// ---------------------------------------------------------------------------
// mma.sync tf32 GEMM: C = act(A @ W^T + bias).
// Persistent CTAs + dynamic tile counter, 128x128x128 tiles, 512 threads,
// warp grid 4m x 4n (each warp: 32x32 out = 2 m-tiles x 4 n-tiles of
// m16n8k8). A double-buffered via cp.async (raw fp32, cvt.rna on fragment
// load); W converted to tf32 once per CTA. Stride-132 smem: all fragment
// LDS patterns bank-conflict-free.
// smem = 3 * 128*132*4 = 202752 B -> 1 CTA/SM.
// ---------------------------------------------------------------------------
#define MMA_TF32(d, a, b0, b1)                                                 \
    asm volatile("mma.sync.aligned.m16n8k8.row.col.f32.tf32.tf32.f32 "         \
                 "{%0,%1,%2,%3}, {%4,%5,%6,%7}, {%8,%9}, {%0,%1,%2,%3};"       \
                 : "+f"((d)[0]), "+f"((d)[1]), "+f"((d)[2]), "+f"((d)[3])      \
                 : "r"((a)[0]), "r"((a)[1]), "r"((a)[2]), "r"((a)[3]),         \
                   "r"(b0), "r"(b1))

__device__ __forceinline__ uint32_t cvt_tf32(float f) {
    uint32_t v;
    asm("cvt.rna.tf32.f32 %0, %1;" : "=r"(v) : "f"(f));
    return v;
}

__device__ __forceinline__ void load_As_async(float* Asb, const float* __restrict__ A,
                                              unsigned t, int nrows, int tid) {
    #pragma unroll
    for (int i = tid; i < 4096; i += 512) {
        int r = i >> 5;
        int c = (i & 31) * 4;
        int gr = (int)t * 128 + r;
        float* dgen = Asb + r * AS_STRIDE + c;
        uint32_t daddr = (uint32_t)__cvta_generic_to_shared(dgen);
        if (gr < nrows) {
            const float* src = A + (size_t)gr * 128 + c;
            asm volatile("cp.async.cg.shared.global [%0], [%1], 16;"
                         :: "r"(daddr), "l"(src));
        } else {
            *(float4*)dgen = make_float4(0.f, 0.f, 0.f, 0.f);
        }
    }
}

template <bool RELU>
__global__ __launch_bounds__(512, 1)
void gemm_mma_kernel(const float* __restrict__ A, const float* __restrict__ W,
                     const float* __restrict__ bias, float* __restrict__ C,
                     int nrows, unsigned* __restrict__ ctr) {
    extern __shared__ float sm[];
    float* Ws  = sm;                        // [128][132]: W[n][k] as tf32 bits
    float* As0 = sm + 128 * AS_STRIDE;
    float* As1 = As0 + 128 * AS_STRIDE;
    __shared__ float s_bias[128];
    __shared__ unsigned s_tile;

    int tid = threadIdx.x;
    int lane = tid & 31;
    int wid = tid >> 5;
    int wm = wid & 3;        // warp row:  rows [wm*32, wm*32+32)
    int wn = wid >> 2;       // warp col:  cols [wn*32, wn*32+32)
    int ntiles = (nrows + 127) >> 7;

    if (tid < 128) s_bias[tid] = bias[tid];

    // W -> tf32 (rna) -> smem, no transpose (B fragment is col-major W[n][k])
    #pragma unroll
    for (int i = tid; i < 4096; i += 512) {
        int r = i >> 5;
        int c = (i & 31) * 4;
        float4 w = *(const float4*)(W + r * 128 + c);
        uint4 u;
        u.x = cvt_tf32(w.x);
        u.y = cvt_tf32(w.y);
        u.z = cvt_tf32(w.z);
        u.w = cvt_tf32(w.w);
        *(uint4*)(Ws + r * AS_STRIDE + c) = u;
    }

    if (tid == 0) s_tile = atomicAdd(ctr, 1u);
    __syncthreads();
    unsigned t = s_tile;
    if (t >= (unsigned)ntiles) return;

    load_As_async(As0, A, t, nrows, tid);
    asm volatile("cp.async.commit_group;");
    int buf = 0;

    int qrow = lane >> 2;    // 0..7
    int qcol = lane & 3;     // 0..3

    while (true) {
        if (tid == 0) s_tile = atomicAdd(ctr, 1u);
        __syncthreads();
        unsigned tn = s_tile;
        bool have_next = (tn < (unsigned)ntiles);
        if (have_next) {
            load_As_async(buf ? As0 : As1, A, tn, nrows, tid);
            asm volatile("cp.async.commit_group;");
            asm volatile("cp.async.wait_group 1;");
        } else {
            asm volatile("cp.async.wait_group 0;");
        }
        __syncthreads();

        const float* Asb = buf ? As1 : As0;
        float acc[2][4][4];
        #pragma unroll
        for (int mt = 0; mt < 2; mt++)
            #pragma unroll
            for (int nt = 0; nt < 4; nt++)
                #pragma unroll
                for (int q = 0; q < 4; q++) acc[mt][nt][q] = 0.0f;

        #pragma unroll 4
        for (int ks = 0; ks < 16; ks++) {
            int k0 = ks * 8;
            uint32_t afrag[2][4];
            #pragma unroll
            for (int mt = 0; mt < 2; mt++) {
                int r0 = wm * 32 + mt * 16 + qrow;
                afrag[mt][0] = cvt_tf32(Asb[r0 * AS_STRIDE + k0 + qcol]);
                afrag[mt][1] = cvt_tf32(Asb[(r0 + 8) * AS_STRIDE + k0 + qcol]);
                afrag[mt][2] = cvt_tf32(Asb[r0 * AS_STRIDE + k0 + qcol + 4]);
                afrag[mt][3] = cvt_tf32(Asb[(r0 + 8) * AS_STRIDE + k0 + qcol + 4]);
            }
            #pragma unroll
            for (int nt = 0; nt < 4; nt++) {
                int n = wn * 32 + nt * 8 + qrow;
                uint32_t b0 = __float_as_uint(Ws[n * AS_STRIDE + k0 + qcol]);
                uint32_t b1 = __float_as_uint(Ws[n * AS_STRIDE + k0 + qcol + 4]);
                MMA_TF32(acc[0][nt], afrag[0], b0, b1);
                MMA_TF32(acc[1][nt], afrag[1], b0, b1);
            }
        }

        // Epilogue: c0,c1 at (row, col..col+1); c2,c3 at (row+8, ...)
        #pragma unroll
        for (int mt = 0; mt < 2; mt++) {
            int grow = (int)t * 128 + wm * 32 + mt * 16 + qrow;
            #pragma unroll
            for (int nt = 0; nt < 4; nt++) {
                int col = wn * 32 + nt * 8 + 2 * qcol;
                float2 o0, o1;
                o0.x = acc[mt][nt][0] + s_bias[col];
                o0.y = acc[mt][nt][1] + s_bias[col + 1];
                o1.x = acc[mt][nt][2] + s_bias[col];
                o1.y = acc[mt][nt][3] + s_bias[col + 1];
                if (RELU) {
                    o0.x = fmaxf(o0.x, 0.0f); o0.y = fmaxf(o0.y, 0.0f);
                    o1.x = fmaxf(o1.x, 0.0f); o1.y = fmaxf(o1.y, 0.0f);
                }
                if (grow < nrows)
                    *(float2*)&C[(size_t)grow * 128 + col] = o0;
                if (grow + 8 < nrows)
                    *(float2*)&C[(size_t)(grow + 8) * 128 + col] = o1;
            }
        }

        if (!have_next) break;
        t = tn;
        buf ^= 1;
    }
}

// ---------------------------------------------------------------------------
extern "C" void kernel_launch(void* const* d_in, const int* in_sizes, int n_in,
                              void* d_out, int out_size) {
    const float* x      = (const float*)d_in[0];
    const int*   ei     = (const int*)d_in[1];
    const float* ew     = (const float*)d_in[2];
    const float* w_edge = (const float*)d_in[3];
    const float* b_edge = (const float*)d_in[4];
    const float* w1     = (const float*)d_in[5];
    const float* b1     = (const float*)d_in[6];
    const float* w2     = (const float*)d_in[7];
    const float* b2     = (const float*)d_in[8];
    float*       out    = (float*)d_out;

    const int smem_bytes = 3 * 128 * AS_STRIDE * sizeof(float);  // 202752
    cudaFuncSetAttribute(gemm_mma_kernel<true>,
                         cudaFuncAttributeMaxDynamicSharedMemorySize, smem_bytes);
    cudaFuncSetAttribute(gemm_mma_kernel<false>,
                         cudaFuncAttributeMaxDynamicSharedMemorySize, smem_bytes);

    float* agg;
    float* h1;
    unsigned* ctr1;
    unsigned* ctr2;
    cudaGetSymbolAddress((void**)&agg, g_agg);
    cudaGetSymbolAddress((void**)&h1, g_h1);
    cudaGetSymbolAddress((void**)&ctr1, g_ctr1);
    cudaGetSymbolAddress((void**)&ctr2, g_ctr2);

    // 1) agg = x ; reset tile counters
    init_agg_kernel<<<2048, 256>>>(x);

    // 2) scatter edges: 4 edges/warp, 8 warps/block
    edge_scatter_kernel<<<N_EDGES / 32, 256>>>(x, ei, ew, w_edge, b_edge);

    // 3) h1 = relu(agg @ w1^T + b1)  — mma.sync tf32
    gemm_mma_kernel<true><<<152, 512, smem_bytes>>>(agg, w1, b1, h1, N_NODES, ctr1);

    // 4) out = h1 @ w2^T + b2
    gemm_mma_kernel<false><<<152, 512, smem_bytes>>>(h1, w2, b2, out, N_NODES, ctr2);
}